// round 7
// baseline (speedup 1.0000x reference)
#include <cuda_runtime.h>
#include <cstdint>

#define HH 48
#define CCH 32
#define PP 56
#define PAD 4
#define X2P_CH (PP*PP*PP)          /* 175616 */
#define X1_CH  (HH*HH*HH)          /* 110592 */

#define TH 4                       /* h-tile */
#define TW 8                       /* w-tile */
#define NSEG 6                     /* 48/8 d-segments */
#define DPT 8
#define NTHREADS 192               /* 32 rows * 6 segs */
#define S2 60                      /* x2 smem row stride: 60 mod 32 = 28 -> conflict-free */
#define S1 52                      /* x1 smem row stride: 52 mod 32 = 20 -> conflict-free */
#define ROWS 32                    /* TH*TW */
#define X2BUF (ROWS*S2)            /* 1920 floats */
#define X1BUF (ROWS*S1)            /* 1664 floats */
#define X1OFF (2*X2BUF)            /* x1 buffers start (floats) */
#define NLD2 448                   /* x2 float4 loads per channel: 32*14 */
#define NLD1 384                   /* x1 float4 loads per channel: 32*12 */

// Zero-padded x2: [C][56][56][56]
__device__ float g_x2p[CCH * X2P_CH];

__global__ void pad_kernel(const float* __restrict__ x2) {
    int idx = blockIdx.x * blockDim.x + threadIdx.x;   // exactly 32*175616 threads
    int c   = idx / X2P_CH;
    int rem = idx % X2P_CH;
    int hp  = rem / (PP*PP);
    int wp  = (rem / PP) % PP;
    int dp  = rem % PP;
    int h = hp - PAD, w = wp - PAD, d = dp - PAD;
    float v = 0.f;
    if ((unsigned)h < HH && (unsigned)w < HH && (unsigned)d < HH)
        v = x2[((c*HH + h)*HH + w)*HH + d];
    g_x2p[idx] = v;
}

__device__ __forceinline__ void cp_async16(uint32_t s, const void* g) {
    asm volatile("cp.async.cg.shared.global [%0], [%1], 16;" :: "r"(s), "l"(g));
}
__device__ __forceinline__ void cp_commit() { asm volatile("cp.async.commit_group;"); }
__device__ __forceinline__ void cp_wait0()  { asm volatile("cp.async.wait_group 0;"); }

// Grid: (6 w-tiles, 12 h-tiles, 81 (oi,oj)). Block: 192 threads, 3 CTAs/SM.
// tid = seg*32 + row  (row-fastest: each warp = one seg, 32 rows -> conflict-free LDS)
// thread owns (h0+lh, w0+lw, seg*8 .. seg*8+7) for all 9 k-offsets.
__global__ void __launch_bounds__(NTHREADS, 3)
corr_kernel(const float* __restrict__ x1, float* __restrict__ out)
{
    __shared__ float smem[2*X2BUF + 2*X1BUF];   /* 7168 floats = 28672 B */

    const int tid = threadIdx.x;
    const int row = tid & 31;            // 0..31 = lh*8 + lw
    const int seg = tid >> 5;            // 0..5 (warp id)
    const int lw  = row & 7;
    const int lh  = row >> 3;
    const int w0  = blockIdx.x * TW;
    const int h0  = blockIdx.y * TH;
    const int ij  = blockIdx.z;
    const int oi  = ij / 9;
    const int oj  = ij % 9;

    uint32_t smem_u32 = (uint32_t)__cvta_generic_to_shared(smem);

    // ---- x2 cooperative-load slots (448 float4 over 192 threads: 3 slots) ----
    uint32_t g2off[3], s2dst[3];
    bool     v2[3];
    #pragma unroll
    for (int s = 0; s < 3; s++) {
        int t = tid + s * NTHREADS;
        v2[s] = (t < NLD2);
        int tt = v2[s] ? t : 0;
        int r = tt / 14, col = tt % 14;
        int hp = h0 + oi + (r >> 3);
        int wp = w0 + oj + (r & 7);
        g2off[s] = (uint32_t)((((hp * PP) + wp) * PP + col * 4) * 4);
        s2dst[s] = smem_u32 + (uint32_t)((r * S2 + col * 4) * 4);
    }
    // ---- x1 cooperative-load slots (384 float4 over 192 threads: 2 slots) ----
    uint32_t g1off[2], s1dst[2];
    #pragma unroll
    for (int s = 0; s < 2; s++) {
        int t = tid + s * NTHREADS;
        int r = t / 12, col = t % 12;
        int hh = h0 + (r >> 3);
        int ww = w0 + (r & 7);
        g1off[s] = (uint32_t)((((hh * HH) + ww) * HH + col * 4) * 4);
        s1dst[s] = smem_u32 + (uint32_t)((X1OFF + r * S1 + col * 4) * 4);
    }

    const char* g2base = (const char*)g_x2p;
    const char* g1base = (const char*)x1;

    float acc[9][DPT];
    #pragma unroll
    for (int k = 0; k < 9; k++)
        #pragma unroll
        for (int r = 0; r < DPT; r++) acc[k][r] = 0.f;

    // Prologue: channel 0 -> buffer 0
    #pragma unroll
    for (int s = 0; s < 3; s++) if (v2[s]) cp_async16(s2dst[s], g2base + g2off[s]);
    #pragma unroll
    for (int s = 0; s < 2; s++) cp_async16(s1dst[s], g1base + g1off[s]);
    cp_commit();

    const int woff = row * S2 + seg * DPT;           // x2 read offset (floats)
    const int xoff = X1OFF + row * S1 + seg * DPT;   // x1 read offset (floats)

    #pragma unroll 1
    for (int c = 0; c < CCH; c++) {
        const int b = c & 1;
        cp_wait0();          // channel c landed in buffer b
        __syncthreads();     // buffer 1-b fully consumed by all threads

        if (c + 1 < CCH) {   // fill other buffer while computing
            const uint32_t nb2 = (uint32_t)(1 - b) * (X2BUF * 4);
            const uint32_t nb1 = (uint32_t)(1 - b) * (X1BUF * 4);
            const char* g2 = g2base + (size_t)(c + 1) * (X2P_CH * 4);
            const char* g1 = g1base + (size_t)(c + 1) * (X1_CH * 4);
            #pragma unroll
            for (int s = 0; s < 3; s++) if (v2[s]) cp_async16(s2dst[s] + nb2, g2 + g2off[s]);
            #pragma unroll
            for (int s = 0; s < 2; s++) cp_async16(s1dst[s] + nb1, g1 + g1off[s]);
            cp_commit();
        }

        const float* wr = smem + b * X2BUF + woff;
        const float* xr = smem + b * X1BUF + xoff;
        float4 q0 = *(const float4*)(wr);
        float4 q1 = *(const float4*)(wr + 4);
        float4 q2 = *(const float4*)(wr + 8);
        float4 q3 = *(const float4*)(wr + 12);
        float4 a0 = *(const float4*)(xr);
        float4 a1 = *(const float4*)(xr + 4);

        float win[16] = {q0.x,q0.y,q0.z,q0.w, q1.x,q1.y,q1.z,q1.w,
                         q2.x,q2.y,q2.z,q2.w, q3.x,q3.y,q3.z,q3.w};
        float xv[8]  = {a0.x,a0.y,a0.z,a0.w, a1.x,a1.y,a1.z,a1.w};

        #pragma unroll
        for (int k = 0; k < 9; k++)
            #pragma unroll
            for (int r = 0; r < DPT; r++)
                acc[k][r] = fmaf(xv[r], win[r + k], acc[k][r]);
    }

    // ---- Epilogue: mean over C, 18 STG.128 (32B-sector aligned per lane) ----
    const float sc = 1.0f / 32.0f;
    size_t base = (size_t)(oi * 81 + oj * 9) * X1_CH
                + ((size_t)(h0 + lh) * HH + (w0 + lw)) * HH + seg * DPT;
    #pragma unroll
    for (int k = 0; k < 9; k++) {
        float4 v0 = make_float4(acc[k][0]*sc, acc[k][1]*sc, acc[k][2]*sc, acc[k][3]*sc);
        float4 v1 = make_float4(acc[k][4]*sc, acc[k][5]*sc, acc[k][6]*sc, acc[k][7]*sc);
        float* p = out + base + (size_t)k * X1_CH;
        *(float4*)(p)     = v0;
        *(float4*)(p + 4) = v1;
    }
}

extern "C" void kernel_launch(void* const* d_in, const int* in_sizes, int n_in,
                              void* d_out, int out_size) {
    const float* x1 = (const float*)d_in[0];
    const float* x2 = (const float*)d_in[1];
    float* out = (float*)d_out;

    pad_kernel<<<21952, 256>>>(x2);   // 32*175616 = 21952*256 threads

    dim3 grid(6, 12, 81);
    corr_kernel<<<grid, NTHREADS>>>(x1, out);
}

// round 8
// speedup vs baseline: 1.1192x; 1.1192x over previous
#include <cuda_runtime.h>
#include <cstdint>

#define HH 48
#define CCH 32
#define PP 56
#define PAD 4
#define X2P_CH (PP*PP*PP)          /* 175616 */
#define X1_CH  (HH*HH*HH)          /* 110592 */

#define TH 4                       /* h-tile */
#define TW 8                       /* w-tile */
#define NSEG 12                    /* 48/4 d-segments */
#define DPT 4
#define NTHREADS 384               /* 32 rows * 12 segs */
#define S2 60                      /* x2 smem row stride: 60 mod 32 = 28 -> conflict-free */
#define S1 52                      /* x1 smem row stride: 52 mod 32 = 20 -> conflict-free */
#define ROWS 32                    /* TH*TW */
#define X2BUF (ROWS*S2)            /* 1920 floats */
#define X1BUF (ROWS*S1)            /* 1664 floats */
#define X1OFF (2*X2BUF)            /* x1 buffers start (floats) */
#define NLD2 448                   /* x2 float4 loads per channel: 32 rows * 14 */
#define NLD1 384                   /* x1 float4 loads per channel: 32 rows * 12 */

// Zero-padded x2: [C][56][56][56]
__device__ float g_x2p[CCH * X2P_CH];

__global__ void pad_kernel(const float* __restrict__ x2) {
    int idx = blockIdx.x * blockDim.x + threadIdx.x;   // exactly 32*175616 threads
    int c   = idx / X2P_CH;
    int rem = idx % X2P_CH;
    int hp  = rem / (PP*PP);
    int wp  = (rem / PP) % PP;
    int dp  = rem % PP;
    int h = hp - PAD, w = wp - PAD, d = dp - PAD;
    float v = 0.f;
    if ((unsigned)h < HH && (unsigned)w < HH && (unsigned)d < HH)
        v = x2[((c*HH + h)*HH + w)*HH + d];
    g_x2p[idx] = v;
}

__device__ __forceinline__ void cp_async16(uint32_t s, const void* g) {
    asm volatile("cp.async.cg.shared.global [%0], [%1], 16;" :: "r"(s), "l"(g));
}
__device__ __forceinline__ void cp_commit() { asm volatile("cp.async.commit_group;"); }
__device__ __forceinline__ void cp_wait0()  { asm volatile("cp.async.wait_group 0;"); }

// Grid: (6 w-tiles, 12 h-tiles, 81 (oi,oj)). Block: 384 threads, 2 CTAs/SM (24 warps).
// tid = seg*32 + row (row-fastest: warp = one d-segment, 32 lanes = 32 (h,w) rows
// -> every 8-lane LDS.128 phase hits distinct banks for strides 60 and 52).
// Thread owns (h0+lh, w0+lw, seg*4 .. seg*4+3) for all 9 k-offsets of (oi,oj).
__global__ void __launch_bounds__(NTHREADS, 2)
corr_kernel(const float* __restrict__ x1, float* __restrict__ out)
{
    __shared__ float smem[2*X2BUF + 2*X1BUF];   /* 7168 floats = 28672 B */

    const int tid = threadIdx.x;
    const int row = tid & 31;            // 0..31 = lh*8 + lw
    const int seg = tid >> 5;            // 0..11 (warp id)
    const int lw  = row & 7;
    const int lh  = row >> 3;
    const int w0  = blockIdx.x * TW;
    const int h0  = blockIdx.y * TH;
    const int ij  = blockIdx.z;
    const int oi  = ij / 9;
    const int oj  = ij % 9;

    uint32_t smem_u32 = (uint32_t)__cvta_generic_to_shared(smem);

    // ---- x2 cooperative-load slots (448 float4 over 384 threads: 2 slots) ----
    uint32_t g2off[2], s2dst[2];
    bool     v2[2];
    #pragma unroll
    for (int s = 0; s < 2; s++) {
        int t = tid + s * NTHREADS;
        v2[s] = (t < NLD2);
        int tt = v2[s] ? t : 0;
        int r = tt / 14, col = tt % 14;
        int hp = h0 + oi + (r >> 3);
        int wp = w0 + oj + (r & 7);
        g2off[s] = (uint32_t)((((hp * PP) + wp) * PP + col * 4) * 4);
        s2dst[s] = smem_u32 + (uint32_t)((r * S2 + col * 4) * 4);
    }
    // ---- x1 cooperative-load slot (384 float4 over 384 threads: 1 slot) ----
    uint32_t g1off, s1dst;
    {
        int r = tid / 12, col = tid % 12;
        int hh = h0 + (r >> 3);
        int ww = w0 + (r & 7);
        g1off = (uint32_t)((((hh * HH) + ww) * HH + col * 4) * 4);
        s1dst = smem_u32 + (uint32_t)((X1OFF + r * S1 + col * 4) * 4);
    }

    const char* g2base = (const char*)g_x2p;
    const char* g1base = (const char*)x1;

    float acc[9][DPT];
    #pragma unroll
    for (int k = 0; k < 9; k++)
        #pragma unroll
        for (int r = 0; r < DPT; r++) acc[k][r] = 0.f;

    // Prologue: channel 0 -> buffer 0
    if (v2[0]) cp_async16(s2dst[0], g2base + g2off[0]);
    if (v2[1]) cp_async16(s2dst[1], g2base + g2off[1]);
    cp_async16(s1dst, g1base + g1off);
    cp_commit();

    const int woff = row * S2 + seg * DPT;           // x2 read offset (floats)
    const int xoff = X1OFF + row * S1 + seg * DPT;   // x1 read offset (floats)

    #pragma unroll 1
    for (int c = 0; c < CCH; c++) {
        const int b = c & 1;
        cp_wait0();          // channel c landed in buffer b
        __syncthreads();     // buffer 1-b fully consumed by all threads

        if (c + 1 < CCH) {   // fill other buffer while computing
            const uint32_t nb2 = (uint32_t)(1 - b) * (X2BUF * 4);
            const uint32_t nb1 = (uint32_t)(1 - b) * (X1BUF * 4);
            const char* g2 = g2base + (size_t)(c + 1) * (X2P_CH * 4);
            const char* g1 = g1base + (size_t)(c + 1) * (X1_CH * 4);
            if (v2[0]) cp_async16(s2dst[0] + nb2, g2 + g2off[0]);
            if (v2[1]) cp_async16(s2dst[1] + nb2, g2 + g2off[1]);
            cp_async16(s1dst + nb1, g1 + g1off);
            cp_commit();
        }

        const float* wr = smem + b * X2BUF + woff;
        const float* xr = smem + b * X1BUF + xoff;
        float4 q0 = *(const float4*)(wr);
        float4 q1 = *(const float4*)(wr + 4);
        float4 q2 = *(const float4*)(wr + 8);
        float4 a0 = *(const float4*)(xr);

        float win[12] = {q0.x,q0.y,q0.z,q0.w, q1.x,q1.y,q1.z,q1.w,
                         q2.x,q2.y,q2.z,q2.w};
        float xv[4]  = {a0.x, a0.y, a0.z, a0.w};

        #pragma unroll
        for (int k = 0; k < 9; k++)
            #pragma unroll
            for (int r = 0; r < DPT; r++)
                acc[k][r] = fmaf(xv[r], win[r + k], acc[k][r]);
    }

    // ---- Epilogue: mean over C, 9 STG.128 ----
    const float sc = 1.0f / 32.0f;
    size_t base = (size_t)(oi * 81 + oj * 9) * X1_CH
                + ((size_t)(h0 + lh) * HH + (w0 + lw)) * HH + seg * DPT;
    #pragma unroll
    for (int k = 0; k < 9; k++) {
        float4 v = make_float4(acc[k][0]*sc, acc[k][1]*sc, acc[k][2]*sc, acc[k][3]*sc);
        *(float4*)(out + base + (size_t)k * X1_CH) = v;
    }
}

extern "C" void kernel_launch(void* const* d_in, const int* in_sizes, int n_in,
                              void* d_out, int out_size) {
    const float* x1 = (const float*)d_in[0];
    const float* x2 = (const float*)d_in[1];
    float* out = (float*)d_out;

    pad_kernel<<<21952, 256>>>(x2);   // 32*175616 = 21952*256 threads

    dim3 grid(6, 12, 81);
    corr_kernel<<<grid, NTHREADS>>>(x1, out);
}